// round 2
// baseline (speedup 1.0000x reference)
#include <cuda_runtime.h>
#include <cuda_fp16.h>
#include <mma.h>

using namespace nvcuda;

#define BATCH 128
#define SEQ   512
#define IDIM  256
#define HDIM  512
#define GDIM  2048   // 4*H

// ---------------- device scratch (static: allocation-guard safe) ----------------
__device__ float  g_xg[2][SEQ][BATCH][GDIM];     // precomputed input-side gates (1 GB)
__device__ __half g_h[2][2][BATCH][HDIM];        // ping-pong recurrent hidden state (fp16)
__device__ __half g_Wih[GDIM][IDIM];             // fp16 converted weights
__device__ __half g_Whh[GDIM][HDIM];
__device__ float  g_bias[GDIM];                  // b_ih + b_hh
__device__ unsigned g_cnt[8];                    // per-group barrier counters

// ---------------- prep: fp32->fp16 weight convert, bias combine, barrier reset ----------------
__global__ void prep_kernel(const float* __restrict__ Wih, const float* __restrict__ Whh,
                            const float* __restrict__ bih, const float* __restrict__ bhh) {
    int idx = blockIdx.x * blockDim.x + threadIdx.x;          // grid covers 1048576
    if (idx < GDIM * IDIM) (&g_Wih[0][0])[idx] = __float2half(Wih[idx]);
    if (idx < GDIM * HDIM) (&g_Whh[0][0])[idx] = __float2half(Whh[idx]);
    if (idx < GDIM)        g_bias[idx] = bih[idx] + bhh[idx];
    if (idx < 8)           g_cnt[idx] = 0u;
}

// ---------------- input projection GEMM: xg[text][s][b][g] = x[b,s,:] @ W_ih[g,:] + bias[g] ----------------
// CTA tile: 64 out-rows x 256 cols, K=256 in 4 chunks of 64. 8 warps, each 32x64 (2x4 wmma frags).
__global__ void __launch_bounds__(256) xgemm_kernel(const float* __restrict__ x0,
                                                    const float* __restrict__ x1) {
    extern __shared__ char sm[];
    half  (*Xs)[72]  = (half (*)[72])sm;                            // 64 x 72 fp16  (9216 B)
    half  (*Ws)[72]  = (half (*)[72])(sm + 64 * 72 * 2);            // 256 x 72 fp16 (36864 B)
    float (*Os)[260] = (float(*)[260])(sm + 64 * 72 * 2 + 256 * 72 * 2); // 64 x 260 f32 (66560 B)

    const int text = blockIdx.z;
    const float* __restrict__ x = text ? x1 : x0;
    const int n0 = blockIdx.x * 256;     // gate-col base (0..1792)
    const int rt = blockIdx.y;           // 0..1023 (64 out-rows each)
    const int s  = rt >> 1;              // sequence index (two row-tiles per s)
    const int b0 = (rt & 1) * 64;        // batch base
    const int tid = threadIdx.x;
    const int w   = tid >> 5;
    const int wm  = (w & 1) * 32;        // warp row offset within tile
    const int wn  = (w >> 1) * 64;       // warp col offset within tile

    wmma::fragment<wmma::accumulator, 16, 16, 16, float> acc[2][4];
#pragma unroll
    for (int i = 0; i < 2; i++)
#pragma unroll
        for (int j = 0; j < 4; j++) wmma::fill_fragment(acc[i][j], 0.0f);

    for (int kc = 0; kc < IDIM; kc += 64) {
        // load X tile: 64 rows x 64 fp32 -> fp16 smem
        {
            int r  = tid >> 2;
            int c0 = (tid & 3) * 16;
            const float4* src = (const float4*)(x + (size_t)(b0 + r) * (SEQ * IDIM) + (size_t)s * IDIM + kc + c0);
#pragma unroll
            for (int v = 0; v < 4; v++) {
                float4 f = src[v];
                half2* d = (half2*)&Xs[r][c0 + v * 4];
                d[0] = __floats2half2_rn(f.x, f.y);
                d[1] = __floats2half2_rn(f.z, f.w);
            }
        }
        // load W tile: 256 rows x 64 fp16
        {
            const uint4* src = (const uint4*)(&g_Wih[n0 + tid][kc]);
            uint4* dst = (uint4*)(&Ws[tid][0]);
#pragma unroll
            for (int v = 0; v < 8; v++) dst[v] = src[v];
        }
        __syncthreads();
#pragma unroll
        for (int kk = 0; kk < 4; kk++) {
            wmma::fragment<wmma::matrix_a, 16, 16, 16, half, wmma::row_major> af[2];
            wmma::load_matrix_sync(af[0], &Xs[wm][kk * 16], 72);
            wmma::load_matrix_sync(af[1], &Xs[wm + 16][kk * 16], 72);
#pragma unroll
            for (int nt = 0; nt < 4; nt++) {
                wmma::fragment<wmma::matrix_b, 16, 16, 16, half, wmma::col_major> bf;
                wmma::load_matrix_sync(bf, &Ws[wn + nt * 16][kk * 16], 72);
                wmma::mma_sync(acc[0][nt], af[0], bf, acc[0][nt]);
                wmma::mma_sync(acc[1][nt], af[1], bf, acc[1][nt]);
            }
        }
        __syncthreads();
    }
    // stage to smem
#pragma unroll
    for (int i = 0; i < 2; i++)
#pragma unroll
        for (int nt = 0; nt < 4; nt++)
            wmma::store_matrix_sync(&Os[wm + i * 16][wn + nt * 16], acc[i][nt], 260, wmma::mem_row_major);
    __syncthreads();

    // write with bias, coalesced float4
#pragma unroll
    for (int v = 0; v < 16; v++) {
        int lin = v * 256 + tid;
        int r = lin >> 6;
        int c = (lin & 63) * 4;
        int R = rt * 64 + r;                 // == s*128 + b
        float4 o;
        o.x = Os[r][c + 0] + g_bias[n0 + c + 0];
        o.y = Os[r][c + 1] + g_bias[n0 + c + 1];
        o.z = Os[r][c + 2] + g_bias[n0 + c + 2];
        o.w = Os[r][c + 3] + g_bias[n0 + c + 3];
        *(float4*)((&g_xg[0][0][0][0]) + ((size_t)text * 65536 + R) * GDIM + n0 + c) = o;
    }
}

// ---------------- recurrence ----------------
// 128 CTAs: text(2) x batch-chunk(4, 32 rows) x gate-slice(16, 128 gate rows / 32 h-cols).
// W_hh slice persistent in SMEM. Per step: GEMM 32x128x512 (wmma, acc preloaded from xg),
// nonlinearity, h-slice write to global, 16-CTA group barrier.
__device__ __forceinline__ void group_barrier(int grp, unsigned target) {
    __threadfence();
    __syncthreads();
    if (threadIdx.x == 0) {
        atomicAdd(&g_cnt[grp], 1u);
        while (*((volatile unsigned*)&g_cnt[grp]) < target) { }
    }
    __syncthreads();
    __threadfence();
}

__global__ void __launch_bounds__(256) lstm_rec_kernel(float* __restrict__ out) {
    extern __shared__ char sm[];
    half  (*Wsh)[520] = (half (*)[520])sm;                              // 128 x 520 (133120 B)
    half  (*Ash)[520] = (half (*)[520])(sm + 133120);                   // 32 x 520  (33280 B)
    float (*Gsh)[132] = (float(*)[132])(sm + 133120 + 33280);           // 32 x 132  (16896 B)
    float (*Csh)[32]  = (float(*)[32]) (sm + 133120 + 33280 + 16896);   // 32 x 32   (4096 B)

    const int bx    = blockIdx.x;
    const int text  = bx >> 6;
    const int chunk = (bx >> 4) & 3;
    const int slice = bx & 15;
    const int grp   = bx >> 4;           // 0..7
    const int tid   = threadIdx.x;
    const int w     = tid >> 5;
    const int wm    = (w & 1) * 16;      // warp M offset (0/16)
    const int nq    = w >> 1;            // gate block (0..3) = 32 local cols

    // load persistent W_hh slice: local row r -> global gate row (r>>5)*512 + slice*32 + (r&31)
#pragma unroll
    for (int v = 0; v < 32; v++) {
        int lin = v * 256 + tid;
        int r = lin >> 6, u = lin & 63;
        int grow = (r >> 5) * HDIM + slice * 32 + (r & 31);
        ((uint4*)&Wsh[r][0])[u] = ((const uint4*)&g_Whh[grow][0])[u];
    }
    // zero cell state
    for (int v = tid; v < 1024; v += 256) (&Csh[0][0])[v] = 0.0f;
    // zero own h slice in ping 0
    if (tid < 128) {
        int b = tid >> 2, u = tid & 3;
        ((uint4*)&g_h[0][text][chunk * 32 + b][slice * 32])[u] = make_uint4(0, 0, 0, 0);
    }

    unsigned nbar = 1;
    group_barrier(grp, nbar * 16); nbar++;   // h(0)=0 visible to whole group

    for (int t = 0; t < SEQ; t++) {
        const int pa = t & 1, pb = pa ^ 1;
        // load full h chunk [32 x 512] fp16 into smem
#pragma unroll
        for (int v = 0; v < 8; v++) {
            int lin = v * 256 + tid;
            int r = lin >> 6, u = lin & 63;
            ((uint4*)&Ash[r][0])[u] = ((const uint4*)&g_h[pa][text][chunk * 32 + r][0])[u];
        }
        __syncthreads();

        // accumulators preloaded from xg (input-side gates, fp32)
        const float* xgp = &g_xg[text][t][chunk * 32 + wm][nq * HDIM + slice * 32];
        wmma::fragment<wmma::accumulator, 16, 16, 16, float> acc[2];
        wmma::load_matrix_sync(acc[0], xgp,      GDIM, wmma::mem_row_major);
        wmma::load_matrix_sync(acc[1], xgp + 16, GDIM, wmma::mem_row_major);

#pragma unroll
        for (int kk = 0; kk < 32; kk++) {
            wmma::fragment<wmma::matrix_a, 16, 16, 16, half, wmma::row_major> af;
            wmma::load_matrix_sync(af, &Ash[wm][kk * 16], 520);
            wmma::fragment<wmma::matrix_b, 16, 16, 16, half, wmma::col_major> bf;
            wmma::load_matrix_sync(bf, &Wsh[nq * 32][kk * 16], 520);
            wmma::mma_sync(acc[0], af, bf, acc[0]);
            wmma::load_matrix_sync(bf, &Wsh[nq * 32 + 16][kk * 16], 520);
            wmma::mma_sync(acc[1], af, bf, acc[1]);
        }
        wmma::store_matrix_sync(&Gsh[wm][nq * 32],      acc[0], 132, wmma::mem_row_major);
        wmma::store_matrix_sync(&Gsh[wm][nq * 32 + 16], acc[1], 132, wmma::mem_row_major);
        __syncthreads();

        // gate nonlinearities + state update (1024 outputs, 4/thread)
#pragma unroll
        for (int e = 0; e < 4; e++) {
            int idx = e * 256 + tid;
            int b = idx >> 5, j = idx & 31;
            float iv = Gsh[b][j];
            float fv = Gsh[b][32 + j];
            float gv = Gsh[b][64 + j];
            float ov = Gsh[b][96 + j];
            iv = 1.0f / (1.0f + __expf(-iv));
            fv = 1.0f / (1.0f + __expf(-fv));
            gv = tanhf(gv);
            ov = 1.0f / (1.0f + __expf(-ov));
            float c = fv * Csh[b][j] + iv * gv;
            Csh[b][j] = c;
            float h = ov * tanhf(c);
            g_h[pb][text][chunk * 32 + b][slice * 32 + j] = __float2half(h);
            if (t == SEQ - 1)
                out[((size_t)text * BATCH + chunk * 32 + b) * HDIM + slice * 32 + j] = h;
        }
        group_barrier(grp, nbar * 16); nbar++;
    }
}

// ---------------- launch ----------------
extern "C" void kernel_launch(void* const* d_in, const int* in_sizes, int n_in,
                              void* d_out, int out_size) {
    (void)in_sizes; (void)n_in; (void)out_size;
    const float* x0  = (const float*)d_in[0];
    const float* x1  = (const float*)d_in[1];
    const float* Wih = (const float*)d_in[2];
    const float* Whh = (const float*)d_in[3];
    const float* bih = (const float*)d_in[4];
    const float* bhh = (const float*)d_in[5];
    float* out = (float*)d_out;

    cudaFuncSetAttribute(xgemm_kernel,    cudaFuncAttributeMaxDynamicSharedMemorySize, 112640);
    cudaFuncSetAttribute(lstm_rec_kernel, cudaFuncAttributeMaxDynamicSharedMemorySize, 187392);

    prep_kernel<<<4096, 256>>>(Wih, Whh, bih, bhh);
    xgemm_kernel<<<dim3(8, 1024, 2), 256, 112640>>>(x0, x1);
    lstm_rec_kernel<<<128, 256, 187392>>>(out);
}